// round 16
// baseline (speedup 1.0000x reference)
#include <cuda_runtime.h>
#include <cuda_fp16.h>
#include <math.h>
#include <stdint.h>

#define B_ 2
#define S_ 2048
#define D_ 1024
#define H_ 16
#define HD_ 64
#define LOG2E 1.4426950408889634f

// fp16 scratch (static device globals: allocation-free)
__device__ __half g_xh[B_*S_*D_];
__device__ __half g_wqh[D_*D_];
__device__ __half g_wkh[D_*D_];
__device__ __half g_wvh[D_*D_];
__device__ __half g_woh[D_*D_];
__device__ __half g_qh[B_*S_*D_];
__device__ __half g_kh[B_*S_*D_];
__device__ __half g_vh[B_*S_*D_];
__device__ __half g_oh[B_*S_*D_];

// ---------------------------------------------------------------------------
// helpers
// ---------------------------------------------------------------------------
__device__ __forceinline__ uint32_t s2u(const void* p) {
    return (uint32_t)__cvta_generic_to_shared(p);
}
__device__ __forceinline__ void ldsm4(uint32_t r[4], uint32_t a) {
    asm volatile("ldmatrix.sync.aligned.m8n8.x4.shared.b16 {%0,%1,%2,%3},[%4];\n"
        : "=r"(r[0]), "=r"(r[1]), "=r"(r[2]), "=r"(r[3]) : "r"(a));
}
__device__ __forceinline__ void ldsm4t(uint32_t r[4], uint32_t a) {
    asm volatile("ldmatrix.sync.aligned.m8n8.x4.trans.shared.b16 {%0,%1,%2,%3},[%4];\n"
        : "=r"(r[0]), "=r"(r[1]), "=r"(r[2]), "=r"(r[3]) : "r"(a));
}
__device__ __forceinline__ void mma_f16(float c[4], const uint32_t a[4], const uint32_t b[2]) {
    asm volatile(
        "mma.sync.aligned.m16n8k16.row.col.f32.f16.f16.f32 "
        "{%0,%1,%2,%3},{%4,%5,%6,%7},{%8,%9},{%0,%1,%2,%3};\n"
        : "+f"(c[0]), "+f"(c[1]), "+f"(c[2]), "+f"(c[3])
        : "r"(a[0]), "r"(a[1]), "r"(a[2]), "r"(a[3]), "r"(b[0]), "r"(b[1]));
}
__device__ __forceinline__ uint32_t pack_h2(float a, float b) {
    __half2 h = __floats2half2_rn(a, b);
    return *reinterpret_cast<uint32_t*>(&h);
}
// fp32 MUFU exp2 (rare path: rescale alpha)
__device__ __forceinline__ float ex2f(float x) {
    float y;
    asm("ex2.approx.ftz.f32 %0,%1;" : "=f"(y) : "f"(x));
    return y;
}
// half2 MUFU exp2: 2 elements per MUFU op, result directly packed
__device__ __forceinline__ uint32_t h2exp2(uint32_t a) {
    uint32_t d;
    asm("ex2.approx.f16x2 %0,%1;" : "=r"(d) : "r"(a));
    return d;
}
#define CP16(dst, src) \
    asm volatile("cp.async.ca.shared.global [%0], [%1], 16;\n" :: "r"(dst), "l"(src))
#define CP_COMMIT() asm volatile("cp.async.commit_group;\n" ::: "memory")
#define CP_WAIT(n)  asm volatile("cp.async.wait_group " #n ";\n" ::: "memory")

// ---------------------------------------------------------------------------
// Fused fp32 -> fp16 convert, MLP=4 (4 independent float4 chunks per thread)
// ---------------------------------------------------------------------------
__global__ void conv_all(
    const float* __restrict__ x,
    const float* __restrict__ wq, const float* __restrict__ wk,
    const float* __restrict__ wv, const float* __restrict__ wo,
    __half* __restrict__ xh,
    __half* __restrict__ wqh, __half* __restrict__ wkh,
    __half* __restrict__ wvh, __half* __restrict__ woh)
{
    const int NX = B_ * S_ * D_;           // 4M
    const int stride4 = gridDim.x * blockDim.x * 4;
    int base = (blockIdx.x * blockDim.x + threadIdx.x) * 4;
    #pragma unroll
    for (int p = 0; p < 4; p++) {
        int i4 = base + p * stride4;
        const float* s; __half* d; int off;
        if (i4 < NX) { s = x; d = xh; off = i4; }
        else {
            int r = i4 - NX;
            int w = r >> 20;               // D_*D_ = 1M = 2^20
            off = r & ((1 << 20) - 1);
            s = (w == 0) ? wq : (w == 1) ? wk : (w == 2) ? wv : wo;
            d = (w == 0) ? wqh : (w == 1) ? wkh : (w == 2) ? wvh : woh;
        }
        float4 v = *(const float4*)(s + off);
        *(__half2*)(d + off)     = __floats2half2_rn(v.x, v.y);
        *(__half2*)(d + off + 2) = __floats2half2_rn(v.z, v.w);
    }
}

// ---------------------------------------------------------------------------
// GEMM body: C[M,N]=A@W+bias, fp16 HMMA fp32-accum.
// Block 128x128, 4 warps (2m x 2n), warp tile 64x64, BK=32, 4-stage cp.async.
// LOAD_FIRST: issue stage s+3 loads before compute(s) (wins when L2-hot,
// e.g. persistent qkv); else compute-then-load (wins when DRAM-cold, gemm_o).
// ---------------------------------------------------------------------------
#define BK 32
#define AS_STRIDE 40
#define BS_STRIDE 136
#define A_ST_SZ (128 * AS_STRIDE)
#define B_ST_SZ (BK * BS_STRIDE)
#define GEMM_SMEM ((4 * (A_ST_SZ + B_ST_SZ)) * 2)

template<bool LOAD_FIRST, typename OT>
__device__ __forceinline__ void gemm_body(
    const __half* __restrict__ A, const __half* __restrict__ W,
    const float* __restrict__ bias, const float* __restrict__ freqs,
    OT* __restrict__ C, int N, int K, int bm, int bn, bool rope, __half* sm)
{
    __half* As = sm;
    __half* Bs = sm + 4 * A_ST_SZ;

    int tid = threadIdx.x, lane = tid & 31, wid = tid >> 5;
    int wm = wid & 1, wn = wid >> 1;          // 2x2 warp grid

    float acc[4][8][4];
    #pragma unroll
    for (int i = 0; i < 4; i++)
        #pragma unroll
        for (int j = 0; j < 8; j++)
            #pragma unroll
            for (int c = 0; c < 4; c++) acc[i][j][c] = 0.f;

    auto load_stage = [&](int s, int buf) {
        int k0 = s * BK;
        __half* ab = As + buf * A_ST_SZ;
        __half* bb = Bs + buf * B_ST_SZ;
        #pragma unroll
        for (int p = 0; p < 4; p++) {          // A: 512 chunks / 128 thr
            int c = tid + p * 128;
            int r = c >> 2, o = (c & 3) * 8;
            CP16(s2u(ab + r * AS_STRIDE + o),
                 A + (size_t)(bm + r) * K + k0 + o);
        }
        #pragma unroll
        for (int p = 0; p < 4; p++) {          // B: 512 chunks / 128 thr
            int c = tid + p * 128;
            int r = c >> 4, o = (c & 15) * 8;
            CP16(s2u(bb + r * BS_STRIDE + o),
                 W + (size_t)(k0 + r) * N + bn + o);
        }
    };

    int a_row = wm * 64 + (lane & 15);
    int a_colh = (lane >> 4) << 3;
    int b_krow = lane & 15;
    int b_coln = (lane >> 4) << 3;

    auto compute = [&](int buf) {
        const __half* ab = As + buf * A_ST_SZ;
        const __half* bb = Bs + buf * B_ST_SZ;
        #pragma unroll
        for (int kk = 0; kk < BK; kk += 16) {
            uint32_t af[4][4], bf[8][2];
            #pragma unroll
            for (int i = 0; i < 4; i++)
                ldsm4(af[i], s2u(ab + (a_row + i * 16) * AS_STRIDE + kk + a_colh));
            #pragma unroll
            for (int jp = 0; jp < 4; jp++) {
                uint32_t r[4];
                ldsm4t(r, s2u(bb + (kk + b_krow) * BS_STRIDE + wn * 64 + jp * 16 + b_coln));
                bf[jp * 2][0] = r[0]; bf[jp * 2][1] = r[1];
                bf[jp * 2 + 1][0] = r[2]; bf[jp * 2 + 1][1] = r[3];
            }
            #pragma unroll
            for (int i = 0; i < 4; i++)
                #pragma unroll
                for (int j = 0; j < 8; j++)
                    mma_f16(acc[i][j], af[i], bf[j]);
        }
    };

    const int NS = K / BK;   // 32
    load_stage(0, 0); CP_COMMIT();
    load_stage(1, 1); CP_COMMIT();
    load_stage(2, 2); CP_COMMIT();

    for (int s = 0; s < NS; s++) {
        CP_WAIT(2);
        __syncthreads();
        if (LOAD_FIRST) {
            if (s + 3 < NS) load_stage(s + 3, (s + 3) & 3);
            CP_COMMIT();
            compute(s & 3);
        } else {
            compute(s & 3);
            if (s + 3 < NS) load_stage(s + 3, (s + 3) & 3);
            CP_COMMIT();
        }
    }
    CP_WAIT(0);   // drain before caller reuses smem

    int r0 = bm + wm * 64 + (lane >> 2);
    int c00 = bn + wn * 64 + (lane & 3) * 2;
    #pragma unroll
    for (int i = 0; i < 4; i++) {
        int row = r0 + i * 16;
        #pragma unroll
        for (int j = 0; j < 8; j++) {
            int col = c00 + j * 8;
            float2 bv = *(const float2*)&bias[col];
            float v0 = acc[i][j][0] + bv.x, v1 = acc[i][j][1] + bv.y;
            float v2 = acc[i][j][2] + bv.x, v3 = acc[i][j][3] + bv.y;
            if (rope) {
                int hp = col & 63;
                float2 c1 = *(const float2*)&freqs[(row & (S_ - 1)) * 64 + hp];
                float2 c2 = *(const float2*)&freqs[((row + 8) & (S_ - 1)) * 64 + hp];
                float t0 = v0 * c1.x - v1 * c1.y;
                float t1 = v0 * c1.y + v1 * c1.x;
                float t2 = v2 * c2.x - v3 * c2.y;
                float t3 = v2 * c2.y + v3 * c2.x;
                v0 = t0; v1 = t1; v2 = t2; v3 = t3;
            }
            if (sizeof(OT) == 4) {
                *(float2*)((float*)C + (size_t)row * N + col)       = make_float2(v0, v1);
                *(float2*)((float*)C + (size_t)(row + 8) * N + col) = make_float2(v2, v3);
            } else {
                *(__half2*)((__half*)C + (size_t)row * N + col)       = __floats2half2_rn(v0, v1);
                *(__half2*)((__half*)C + (size_t)(row + 8) * N + col) = __floats2half2_rn(v2, v3);
            }
        }
    }
}

// Persistent fused QKV: 768 tiles over a fixed grid. z fastest (L2 A-reuse).
__global__ __launch_bounds__(128) void gemm_qkv_p(
    const __half* __restrict__ A,
    const __half* __restrict__ w0, const __half* __restrict__ w1,
    const __half* __restrict__ w2,
    const float* __restrict__ b0, const float* __restrict__ b1,
    const float* __restrict__ b2,
    const float* __restrict__ freqs,
    __half* __restrict__ c0, __half* __restrict__ c1, __half* __restrict__ c2)
{
    extern __shared__ __half smq[];
    const int NTILE = 3 * (D_ / 128) * ((B_ * S_) / 128);   // 768
    for (int t = blockIdx.x; t < NTILE; t += gridDim.x) {
        int z = t % 3;
        int t2 = t / 3;
        int bx = t2 & 7, by = t2 >> 3;
        const __half* W = (z == 0) ? w0 : (z == 1) ? w1 : w2;
        const float* bb = (z == 0) ? b0 : (z == 1) ? b1 : b2;
        __half* C = (z == 0) ? c0 : (z == 1) ? c1 : c2;
        __syncthreads();   // protect smem reuse across tiles
        gemm_body<true, __half>(A, W, bb, freqs, C, D_, D_, by * 128, bx * 128, z < 2, smq);
    }
}

// Output projection (256 CTAs < 1 wave: plain grid, compute-first order)
__global__ __launch_bounds__(128) void gemm_o(
    const __half* __restrict__ A, const __half* __restrict__ W,
    const float* __restrict__ bias, float* __restrict__ C)
{
    extern __shared__ __half smo[];
    gemm_body<false, float>(A, W, bias, (const float*)nullptr, C, D_, D_,
                            blockIdx.y * 128, blockIdx.x * 128, false, smo);
}

// ---------------------------------------------------------------------------
// Flash attention, fp16 HMMA, persistent grid, 3-buffer KV ring (wait_group 1:
// each KV tile gets 2 iterations of latency cover).
// Work item: (q-tile, h, b); 4 warps x 32q (2 groups of 16).
// ---------------------------------------------------------------------------
#define QKV_STRIDE 72
#define Q_SZ (128 * QKV_STRIDE)
#define KV_SZ (64 * QKV_STRIDE)
#define ATTN_SMEM ((Q_SZ + 6 * KV_SZ) * 2)

__global__ __launch_bounds__(128) void attn_mma_p(
    const __half* __restrict__ Q, const __half* __restrict__ K,
    const __half* __restrict__ V, __half* __restrict__ O)
{
    extern __shared__ __half asm_[];
    __half* Qs = asm_;
    __half* Ks = asm_ + Q_SZ;                 // [3][KV_SZ]
    __half* Vs = asm_ + Q_SZ + 3 * KV_SZ;     // [3][KV_SZ]

    int tid = threadIdx.x, lane = tid & 31, wid = tid >> 5;
    const int NWORK = (S_ / 128) * H_ * B_;   // 512
    const int NT = S_ / 64;                   // 32

    for (int w = blockIdx.x; w < NWORK; w += gridDim.x) {
        int qt = w & 15;              // q-tile fastest: L2 K/V reuse
        int h = (w >> 4) & 15;
        int b = w >> 8;
        int q0 = qt * 128;
        const size_t base = (size_t)b * S_ * D_ + h * HD_;

        __syncthreads();   // protect smem reuse across work items

        #pragma unroll
        for (int p = 0; p < 8; p++) {
            int c = tid + p * 128;
            int row = c >> 3, off = (c & 7) * 8;
            CP16(s2u(Qs + row * QKV_STRIDE + off),
                 Q + base + (size_t)(q0 + row) * D_ + off);
        }
        CP_COMMIT();

        auto load_kv = [&](int t, int buf) {
            __half* kb = Ks + buf * KV_SZ;
            __half* vb = Vs + buf * KV_SZ;
            #pragma unroll
            for (int p = 0; p < 8; p++) {
                int c = tid + p * 128;
                int row = (c >> 3) & 63, off = (c & 7) * 8;
                if (c < 512)
                    CP16(s2u(kb + row * QKV_STRIDE + off),
                         K + base + (size_t)(t * 64 + row) * D_ + off);
                else
                    CP16(s2u(vb + row * QKV_STRIDE + off),
                         V + base + (size_t)(t * 64 + row) * D_ + off);
            }
        };
        load_kv(0, 0); CP_COMMIT();
        load_kv(1, 1); CP_COMMIT();

        CP_WAIT(2);   // Q arrived (kv0/kv1 may still fly)
        __syncthreads();

        uint32_t aq[2][4][4];
        {
            int ch = (lane >> 4) << 3;
            #pragma unroll
            for (int g = 0; g < 2; g++) {
                int r = wid * 32 + g * 16 + (lane & 15);
                #pragma unroll
                for (int kt = 0; kt < 4; kt++)
                    ldsm4(aq[g][kt], s2u(Qs + r * QKV_STRIDE + kt * 16 + ch));
            }
        }

        float of[2][8][4];
        #pragma unroll
        for (int g = 0; g < 2; g++)
            #pragma unroll
            for (int j = 0; j < 8; j++)
                #pragma unroll
                for (int c = 0; c < 4; c++) of[g][j][c] = 0.f;
        float m_[2][2] = {{-1e30f, -1e30f}, {-1e30f, -1e30f}};
        float l_[2][2] = {{0.f, 0.f}, {0.f, 0.f}};
        const float cs_ = 0.125f * LOG2E;
        const uint32_t ones2 = 0x3C003C00u;
        const uint32_t ob[2] = { ones2, ones2 };

        int buf = 0;
        for (int t = 0; t < NT; t++) {
            if (t == NT - 1) CP_WAIT(0); else CP_WAIT(1);   // tile t resident
            __syncthreads();
            {   // always load+commit (tail reloads last tile into dead buffer)
                int tn = t + 2 < NT ? t + 2 : NT - 1;
                int nb = buf + 2; if (nb >= 3) nb -= 3;
                load_kv(tn, nb);
                CP_COMMIT();
            }

            const __half* kb = Ks + buf * KV_SZ;
            const __half* vb = Vs + buf * KV_SZ;

            float sf[2][8][4];
            #pragma unroll
            for (int g = 0; g < 2; g++)
                #pragma unroll
                for (int j = 0; j < 8; j++)
                    #pragma unroll
                    for (int c = 0; c < 4; c++) sf[g][j][c] = 0.f;

            #pragma unroll
            for (int kt = 0; kt < 4; kt++) {
                #pragma unroll
                for (int jp = 0; jp < 4; jp++) {
                    uint32_t rr[4];
                    ldsm4(rr, s2u(kb + (jp * 16 + (lane & 15)) * QKV_STRIDE +
                                  kt * 16 + ((lane >> 4) << 3)));
                    uint32_t blo[2] = { rr[0], rr[2] };
                    uint32_t bhi[2] = { rr[1], rr[3] };
                    mma_f16(sf[0][jp * 2], aq[0][kt], blo);
                    mma_f16(sf[0][jp * 2 + 1], aq[0][kt], bhi);
                    mma_f16(sf[1][jp * 2], aq[1][kt], blo);
                    mma_f16(sf[1][jp * 2 + 1], aq[1][kt], bhi);
                }
            }

            uint32_t pa[2][4][4];
            #pragma unroll
            for (int g = 0; g < 2; g++) {
                float mx0 = -1e30f, mx1 = -1e30f;
                #pragma unroll
                for (int j = 0; j < 8; j++) {
                    mx0 = fmaxf(mx0, fmaxf(sf[g][j][0], sf[g][j][1]));
                    mx1 = fmaxf(mx1, fmaxf(sf[g][j][2], sf[g][j][3]));
                }
                mx0 = fmaxf(mx0, __shfl_xor_sync(0xffffffffu, mx0, 1, 4));
                mx0 = fmaxf(mx0, __shfl_xor_sync(0xffffffffu, mx0, 2, 4));
                mx1 = fmaxf(mx1, __shfl_xor_sync(0xffffffffu, mx1, 1, 4));
                mx1 = fmaxf(mx1, __shfl_xor_sync(0xffffffffu, mx1, 2, 4));

                if (mx0 > m_[g][0]) {
                    float alpha = ex2f((m_[g][0] - mx0) * cs_);
                    m_[g][0] = mx0; l_[g][0] *= alpha;
                    #pragma unroll
                    for (int j = 0; j < 8; j++) { of[g][j][0] *= alpha; of[g][j][1] *= alpha; }
                }
                if (mx1 > m_[g][1]) {
                    float alpha = ex2f((m_[g][1] - mx1) * cs_);
                    m_[g][1] = mx1; l_[g][1] *= alpha;
                    #pragma unroll
                    for (int j = 0; j < 8; j++) { of[g][j][2] *= alpha; of[g][j][3] *= alpha; }
                }

                float nm0 = -m_[g][0] * cs_, nm1 = -m_[g][1] * cs_;
                #pragma unroll
                for (int kk = 0; kk < 4; kk++) {
                    int ja = 2 * kk, jb = 2 * kk + 1;
                    pa[g][kk][0] = h2exp2(pack_h2(fmaf(sf[g][ja][0], cs_, nm0),
                                                  fmaf(sf[g][ja][1], cs_, nm0)));
                    pa[g][kk][1] = h2exp2(pack_h2(fmaf(sf[g][ja][2], cs_, nm1),
                                                  fmaf(sf[g][ja][3], cs_, nm1)));
                    pa[g][kk][2] = h2exp2(pack_h2(fmaf(sf[g][jb][0], cs_, nm0),
                                                  fmaf(sf[g][jb][1], cs_, nm0)));
                    pa[g][kk][3] = h2exp2(pack_h2(fmaf(sf[g][jb][2], cs_, nm1),
                                                  fmaf(sf[g][jb][3], cs_, nm1)));
                }

                float lacc[4] = { 0.f, 0.f, 0.f, 0.f };
                #pragma unroll
                for (int kk = 0; kk < 4; kk++)
                    mma_f16(lacc, pa[g][kk], ob);
                l_[g][0] += lacc[0];
                l_[g][1] += lacc[2];
            }

            #pragma unroll
            for (int kk = 0; kk < 4; kk++) {
                #pragma unroll
                for (int jp = 0; jp < 4; jp++) {
                    uint32_t rr[4];
                    ldsm4t(rr, s2u(vb + (kk * 16 + (lane & 15)) * QKV_STRIDE +
                                   jp * 16 + ((lane >> 4) << 3)));
                    uint32_t blo[2] = { rr[0], rr[1] };
                    uint32_t bhi[2] = { rr[2], rr[3] };
                    mma_f16(of[0][jp * 2], pa[0][kk], blo);
                    mma_f16(of[0][jp * 2 + 1], pa[0][kk], bhi);
                    mma_f16(of[1][jp * 2], pa[1][kk], blo);
                    mma_f16(of[1][jp * 2 + 1], pa[1][kk], bhi);
                }
            }

            if (++buf == 3) buf = 0;
        }

        #pragma unroll
        for (int g = 0; g < 2; g++) {
            float inv0 = 1.f / l_[g][0], inv1 = 1.f / l_[g][1];
            int r = wid * 32 + g * 16 + (lane >> 2);
            int c0 = (lane & 3) * 2;
            #pragma unroll
            for (int j = 0; j < 8; j++) {
                int col = j * 8 + c0;
                *(__half2*)(O + base + (size_t)(q0 + r) * D_ + col) =
                    __floats2half2_rn(of[g][j][0] * inv0, of[g][j][1] * inv0);
                *(__half2*)(O + base + (size_t)(q0 + r + 8) * D_ + col) =
                    __floats2half2_rn(of[g][j][2] * inv1, of[g][j][3] * inv1);
            }
        }
        CP_WAIT(0);   // drain tail loads before next work item's smem writes
    }
}

// ---------------------------------------------------------------------------
// Launch
// ---------------------------------------------------------------------------
extern "C" void kernel_launch(void* const* d_in, const int* in_sizes, int n_in,
                              void* d_out, int out_size)
{
    const float* x  = (const float*)d_in[0];
    const float* fr = (const float*)d_in[1];
    const float* wq = (const float*)d_in[2];
    const float* bq = (const float*)d_in[3];
    const float* wk = (const float*)d_in[4];
    const float* bk = (const float*)d_in[5];
    const float* wv = (const float*)d_in[6];
    const float* bv = (const float*)d_in[7];
    const float* wo = (const float*)d_in[8];
    const float* bo = (const float*)d_in[9];
    float* out = (float*)d_out;

    __half *xh, *wqh, *wkh, *wvh, *woh, *qh, *kh, *vh, *oh;
    cudaGetSymbolAddress((void**)&xh,  g_xh);
    cudaGetSymbolAddress((void**)&wqh, g_wqh);
    cudaGetSymbolAddress((void**)&wkh, g_wkh);
    cudaGetSymbolAddress((void**)&wvh, g_wvh);
    cudaGetSymbolAddress((void**)&woh, g_woh);
    cudaGetSymbolAddress((void**)&qh,  g_qh);
    cudaGetSymbolAddress((void**)&kh,  g_kh);
    cudaGetSymbolAddress((void**)&vh,  g_vh);
    cudaGetSymbolAddress((void**)&oh,  g_oh);

    cudaFuncSetAttribute(gemm_qkv_p,
                         cudaFuncAttributeMaxDynamicSharedMemorySize, GEMM_SMEM);
    cudaFuncSetAttribute(gemm_o,
                         cudaFuncAttributeMaxDynamicSharedMemorySize, GEMM_SMEM);
    cudaFuncSetAttribute(attn_mma_p,
                         cudaFuncAttributeMaxDynamicSharedMemorySize, ATTN_SMEM);

    int dev = 0, nsm = 148;
    cudaGetDevice(&dev);
    cudaDeviceGetAttribute(&nsm, cudaDevAttrMultiProcessorCount, dev);
    int pgrid = 2 * nsm;   // 2 CTAs/SM residency for both persistent kernels

    const int NTOT = B_ * S_ * D_ + 4 * D_ * D_;   // 8M elements
    conv_all<<<NTOT / 4096, 256>>>(x, wq, wk, wv, wo, xh, wqh, wkh, wvh, woh);

    gemm_qkv_p<<<pgrid, 128, GEMM_SMEM>>>(xh, wqh, wkh, wvh, bq, bk, bv, fr,
                                          qh, kh, vh);

    attn_mma_p<<<pgrid, 128, ATTN_SMEM>>>(qh, kh, vh, oh);

    dim3 gg(D_ / 128, (B_ * S_) / 128);      // (8, 32)
    gemm_o<<<gg, 128, GEMM_SMEM>>>(oh, woh, bo, out);
}

// round 17
// speedup vs baseline: 1.0171x; 1.0171x over previous
#include <cuda_runtime.h>
#include <cuda_fp16.h>
#include <math.h>
#include <stdint.h>

#define B_ 2
#define S_ 2048
#define D_ 1024
#define H_ 16
#define HD_ 64
#define LOG2E 1.4426950408889634f

// fp16 scratch (static device globals: allocation-free)
__device__ __half g_xh[B_*S_*D_];
__device__ __half g_wqh[D_*D_];
__device__ __half g_wkh[D_*D_];
__device__ __half g_wvh[D_*D_];
__device__ __half g_woh[D_*D_];
__device__ __half g_qh[B_*S_*D_];
__device__ __half g_kh[B_*S_*D_];
__device__ __half g_vh[B_*S_*D_];
__device__ __half g_oh[B_*S_*D_];

// ---------------------------------------------------------------------------
// helpers
// ---------------------------------------------------------------------------
__device__ __forceinline__ uint32_t s2u(const void* p) {
    return (uint32_t)__cvta_generic_to_shared(p);
}
__device__ __forceinline__ void ldsm4(uint32_t r[4], uint32_t a) {
    asm volatile("ldmatrix.sync.aligned.m8n8.x4.shared.b16 {%0,%1,%2,%3},[%4];\n"
        : "=r"(r[0]), "=r"(r[1]), "=r"(r[2]), "=r"(r[3]) : "r"(a));
}
__device__ __forceinline__ void ldsm4t(uint32_t r[4], uint32_t a) {
    asm volatile("ldmatrix.sync.aligned.m8n8.x4.trans.shared.b16 {%0,%1,%2,%3},[%4];\n"
        : "=r"(r[0]), "=r"(r[1]), "=r"(r[2]), "=r"(r[3]) : "r"(a));
}
__device__ __forceinline__ void mma_f16(float c[4], const uint32_t a[4], const uint32_t b[2]) {
    asm volatile(
        "mma.sync.aligned.m16n8k16.row.col.f32.f16.f16.f32 "
        "{%0,%1,%2,%3},{%4,%5,%6,%7},{%8,%9},{%0,%1,%2,%3};\n"
        : "+f"(c[0]), "+f"(c[1]), "+f"(c[2]), "+f"(c[3])
        : "r"(a[0]), "r"(a[1]), "r"(a[2]), "r"(a[3]), "r"(b[0]), "r"(b[1]));
}
__device__ __forceinline__ uint32_t pack_h2(float a, float b) {
    __half2 h = __floats2half2_rn(a, b);
    return *reinterpret_cast<uint32_t*>(&h);
}
// fp32 MUFU exp2 (rare path: rescale alpha)
__device__ __forceinline__ float ex2f(float x) {
    float y;
    asm("ex2.approx.ftz.f32 %0,%1;" : "=f"(y) : "f"(x));
    return y;
}
// half2 MUFU exp2: 2 elements per MUFU op, result directly packed
__device__ __forceinline__ uint32_t h2exp2(uint32_t a) {
    uint32_t d;
    asm("ex2.approx.f16x2 %0,%1;" : "=r"(d) : "r"(a));
    return d;
}
#define CP16(dst, src) \
    asm volatile("cp.async.ca.shared.global [%0], [%1], 16;\n" :: "r"(dst), "l"(src))
#define CP_COMMIT() asm volatile("cp.async.commit_group;\n" ::: "memory")
#define CP_WAIT(n)  asm volatile("cp.async.wait_group " #n ";\n" ::: "memory")

// ---------------------------------------------------------------------------
// Fused fp32 -> fp16 convert, MLP=4 (4 independent float4 chunks per thread)
// ---------------------------------------------------------------------------
__global__ void conv_all(
    const float* __restrict__ x,
    const float* __restrict__ wq, const float* __restrict__ wk,
    const float* __restrict__ wv, const float* __restrict__ wo,
    __half* __restrict__ xh,
    __half* __restrict__ wqh, __half* __restrict__ wkh,
    __half* __restrict__ wvh, __half* __restrict__ woh)
{
    const int NX = B_ * S_ * D_;           // 4M
    const int stride4 = gridDim.x * blockDim.x * 4;
    int base = (blockIdx.x * blockDim.x + threadIdx.x) * 4;
    #pragma unroll
    for (int p = 0; p < 4; p++) {
        int i4 = base + p * stride4;
        const float* s; __half* d; int off;
        if (i4 < NX) { s = x; d = xh; off = i4; }
        else {
            int r = i4 - NX;
            int w = r >> 20;               // D_*D_ = 1M = 2^20
            off = r & ((1 << 20) - 1);
            s = (w == 0) ? wq : (w == 1) ? wk : (w == 2) ? wv : wo;
            d = (w == 0) ? wqh : (w == 1) ? wkh : (w == 2) ? wvh : woh;
        }
        float4 v = *(const float4*)(s + off);
        *(__half2*)(d + off)     = __floats2half2_rn(v.x, v.y);
        *(__half2*)(d + off + 2) = __floats2half2_rn(v.z, v.w);
    }
}

// ---------------------------------------------------------------------------
// GEMM body: C[M,N]=A@W+bias, fp16 HMMA fp32-accum.
// Block 128x128, 4 warps (2m x 2n), warp tile 64x64, BK=32, 4-stage cp.async.
// LOAD_FIRST: issue stage s+3 loads before compute(s) (wins when L2-hot,
// e.g. persistent qkv); else compute-then-load (wins when DRAM-cold, gemm_o).
// ---------------------------------------------------------------------------
#define BK 32
#define AS_STRIDE 40
#define BS_STRIDE 136
#define A_ST_SZ (128 * AS_STRIDE)
#define B_ST_SZ (BK * BS_STRIDE)
#define GEMM_SMEM ((4 * (A_ST_SZ + B_ST_SZ)) * 2)

template<bool LOAD_FIRST, typename OT>
__device__ __forceinline__ void gemm_body(
    const __half* __restrict__ A, const __half* __restrict__ W,
    const float* __restrict__ bias, const float* __restrict__ freqs,
    OT* __restrict__ C, int N, int K, int bm, int bn, bool rope, __half* sm)
{
    __half* As = sm;
    __half* Bs = sm + 4 * A_ST_SZ;

    int tid = threadIdx.x, lane = tid & 31, wid = tid >> 5;
    int wm = wid & 1, wn = wid >> 1;          // 2x2 warp grid

    float acc[4][8][4];
    #pragma unroll
    for (int i = 0; i < 4; i++)
        #pragma unroll
        for (int j = 0; j < 8; j++)
            #pragma unroll
            for (int c = 0; c < 4; c++) acc[i][j][c] = 0.f;

    auto load_stage = [&](int s, int buf) {
        int k0 = s * BK;
        __half* ab = As + buf * A_ST_SZ;
        __half* bb = Bs + buf * B_ST_SZ;
        #pragma unroll
        for (int p = 0; p < 4; p++) {          // A: 512 chunks / 128 thr
            int c = tid + p * 128;
            int r = c >> 2, o = (c & 3) * 8;
            CP16(s2u(ab + r * AS_STRIDE + o),
                 A + (size_t)(bm + r) * K + k0 + o);
        }
        #pragma unroll
        for (int p = 0; p < 4; p++) {          // B: 512 chunks / 128 thr
            int c = tid + p * 128;
            int r = c >> 4, o = (c & 15) * 8;
            CP16(s2u(bb + r * BS_STRIDE + o),
                 W + (size_t)(k0 + r) * N + bn + o);
        }
    };

    int a_row = wm * 64 + (lane & 15);
    int a_colh = (lane >> 4) << 3;
    int b_krow = lane & 15;
    int b_coln = (lane >> 4) << 3;

    auto compute = [&](int buf) {
        const __half* ab = As + buf * A_ST_SZ;
        const __half* bb = Bs + buf * B_ST_SZ;
        #pragma unroll
        for (int kk = 0; kk < BK; kk += 16) {
            uint32_t af[4][4], bf[8][2];
            #pragma unroll
            for (int i = 0; i < 4; i++)
                ldsm4(af[i], s2u(ab + (a_row + i * 16) * AS_STRIDE + kk + a_colh));
            #pragma unroll
            for (int jp = 0; jp < 4; jp++) {
                uint32_t r[4];
                ldsm4t(r, s2u(bb + (kk + b_krow) * BS_STRIDE + wn * 64 + jp * 16 + b_coln));
                bf[jp * 2][0] = r[0]; bf[jp * 2][1] = r[1];
                bf[jp * 2 + 1][0] = r[2]; bf[jp * 2 + 1][1] = r[3];
            }
            #pragma unroll
            for (int i = 0; i < 4; i++)
                #pragma unroll
                for (int j = 0; j < 8; j++)
                    mma_f16(acc[i][j], af[i], bf[j]);
        }
    };

    const int NS = K / BK;   // 32
    load_stage(0, 0); CP_COMMIT();
    load_stage(1, 1); CP_COMMIT();
    load_stage(2, 2); CP_COMMIT();

    for (int s = 0; s < NS; s++) {
        CP_WAIT(2);
        __syncthreads();
        if (LOAD_FIRST) {
            if (s + 3 < NS) load_stage(s + 3, (s + 3) & 3);
            CP_COMMIT();
            compute(s & 3);
        } else {
            compute(s & 3);
            if (s + 3 < NS) load_stage(s + 3, (s + 3) & 3);
            CP_COMMIT();
        }
    }
    CP_WAIT(0);   // drain before caller reuses smem

    int r0 = bm + wm * 64 + (lane >> 2);
    int c00 = bn + wn * 64 + (lane & 3) * 2;
    #pragma unroll
    for (int i = 0; i < 4; i++) {
        int row = r0 + i * 16;
        #pragma unroll
        for (int j = 0; j < 8; j++) {
            int col = c00 + j * 8;
            float2 bv = *(const float2*)&bias[col];
            float v0 = acc[i][j][0] + bv.x, v1 = acc[i][j][1] + bv.y;
            float v2 = acc[i][j][2] + bv.x, v3 = acc[i][j][3] + bv.y;
            if (rope) {
                int hp = col & 63;
                float2 c1 = *(const float2*)&freqs[(row & (S_ - 1)) * 64 + hp];
                float2 c2 = *(const float2*)&freqs[((row + 8) & (S_ - 1)) * 64 + hp];
                float t0 = v0 * c1.x - v1 * c1.y;
                float t1 = v0 * c1.y + v1 * c1.x;
                float t2 = v2 * c2.x - v3 * c2.y;
                float t3 = v2 * c2.y + v3 * c2.x;
                v0 = t0; v1 = t1; v2 = t2; v3 = t3;
            }
            if (sizeof(OT) == 4) {
                *(float2*)((float*)C + (size_t)row * N + col)       = make_float2(v0, v1);
                *(float2*)((float*)C + (size_t)(row + 8) * N + col) = make_float2(v2, v3);
            } else {
                *(__half2*)((__half*)C + (size_t)row * N + col)       = __floats2half2_rn(v0, v1);
                *(__half2*)((__half*)C + (size_t)(row + 8) * N + col) = __floats2half2_rn(v2, v3);
            }
        }
    }
}

// Persistent fused QKV: 768 tiles over a fixed grid. z fastest (L2 A-reuse).
__global__ __launch_bounds__(128) void gemm_qkv_p(
    const __half* __restrict__ A,
    const __half* __restrict__ w0, const __half* __restrict__ w1,
    const __half* __restrict__ w2,
    const float* __restrict__ b0, const float* __restrict__ b1,
    const float* __restrict__ b2,
    const float* __restrict__ freqs,
    __half* __restrict__ c0, __half* __restrict__ c1, __half* __restrict__ c2)
{
    extern __shared__ __half smq[];
    const int NTILE = 3 * (D_ / 128) * ((B_ * S_) / 128);   // 768
    for (int t = blockIdx.x; t < NTILE; t += gridDim.x) {
        int z = t % 3;
        int t2 = t / 3;
        int bx = t2 & 7, by = t2 >> 3;
        const __half* W = (z == 0) ? w0 : (z == 1) ? w1 : w2;
        const float* bb = (z == 0) ? b0 : (z == 1) ? b1 : b2;
        __half* C = (z == 0) ? c0 : (z == 1) ? c1 : c2;
        __syncthreads();   // protect smem reuse across tiles
        gemm_body<true, __half>(A, W, bb, freqs, C, D_, D_, by * 128, bx * 128, z < 2, smq);
    }
}

// Output projection (256 CTAs < 1 wave: plain grid, compute-first order)
__global__ __launch_bounds__(128) void gemm_o(
    const __half* __restrict__ A, const __half* __restrict__ W,
    const float* __restrict__ bias, float* __restrict__ C)
{
    extern __shared__ __half smo[];
    gemm_body<false, float>(A, W, bias, (const float*)nullptr, C, D_, D_,
                            blockIdx.y * 128, blockIdx.x * 128, false, smo);
}

// ---------------------------------------------------------------------------
// Flash attention, fp16 HMMA, persistent grid, double-buffered KV (R15).
// l row-sum MMAs issued AFTER PV MMAs (shorter exp->PV critical path).
// Work item: (q-tile, h, b); 4 warps x 32q (2 groups of 16).
// ---------------------------------------------------------------------------
#define QKV_STRIDE 72
#define Q_SZ (128 * QKV_STRIDE)
#define KV_SZ (64 * QKV_STRIDE)
#define ATTN_SMEM ((Q_SZ + 4 * KV_SZ) * 2)

__global__ __launch_bounds__(128) void attn_mma_p(
    const __half* __restrict__ Q, const __half* __restrict__ K,
    const __half* __restrict__ V, __half* __restrict__ O)
{
    extern __shared__ __half asm_[];
    __half* Qs = asm_;
    __half* Ks = asm_ + Q_SZ;
    __half* Vs = asm_ + Q_SZ + 2 * KV_SZ;

    int tid = threadIdx.x, lane = tid & 31, wid = tid >> 5;
    const int NWORK = (S_ / 128) * H_ * B_;   // 512

    for (int w = blockIdx.x; w < NWORK; w += gridDim.x) {
        int qt = w & 15;              // q-tile fastest: L2 K/V reuse
        int h = (w >> 4) & 15;
        int b = w >> 8;
        int q0 = qt * 128;
        const size_t base = (size_t)b * S_ * D_ + h * HD_;

        __syncthreads();   // protect smem reuse across work items

        #pragma unroll
        for (int p = 0; p < 8; p++) {
            int c = tid + p * 128;
            int row = c >> 3, off = (c & 7) * 8;
            CP16(s2u(Qs + row * QKV_STRIDE + off),
                 Q + base + (size_t)(q0 + row) * D_ + off);
        }
        CP_COMMIT();

        auto load_kv = [&](int t, int buf) {
            __half* kb = Ks + buf * KV_SZ;
            __half* vb = Vs + buf * KV_SZ;
            #pragma unroll
            for (int p = 0; p < 8; p++) {
                int c = tid + p * 128;
                int row = (c >> 3) & 63, off = (c & 7) * 8;
                if (c < 512)
                    CP16(s2u(kb + row * QKV_STRIDE + off),
                         K + base + (size_t)(t * 64 + row) * D_ + off);
                else
                    CP16(s2u(vb + row * QKV_STRIDE + off),
                         V + base + (size_t)(t * 64 + row) * D_ + off);
            }
        };
        load_kv(0, 0); CP_COMMIT();

        CP_WAIT(1);
        __syncthreads();

        uint32_t aq[2][4][4];
        {
            int ch = (lane >> 4) << 3;
            #pragma unroll
            for (int g = 0; g < 2; g++) {
                int r = wid * 32 + g * 16 + (lane & 15);
                #pragma unroll
                for (int kt = 0; kt < 4; kt++)
                    ldsm4(aq[g][kt], s2u(Qs + r * QKV_STRIDE + kt * 16 + ch));
            }
        }

        float of[2][8][4];
        #pragma unroll
        for (int g = 0; g < 2; g++)
            #pragma unroll
            for (int j = 0; j < 8; j++)
                #pragma unroll
                for (int c = 0; c < 4; c++) of[g][j][c] = 0.f;
        float m_[2][2] = {{-1e30f, -1e30f}, {-1e30f, -1e30f}};
        float l_[2][2] = {{0.f, 0.f}, {0.f, 0.f}};
        const float cs_ = 0.125f * LOG2E;
        const uint32_t ones2 = 0x3C003C00u;
        const uint32_t ob[2] = { ones2, ones2 };

        for (int t = 0; t < S_ / 64; t++) {
            CP_WAIT(0);
            __syncthreads();
            if (t + 1 < S_ / 64) load_kv(t + 1, (t + 1) & 1);
            CP_COMMIT();

            const __half* kb = Ks + (t & 1) * KV_SZ;
            const __half* vb = Vs + (t & 1) * KV_SZ;

            float sf[2][8][4];
            #pragma unroll
            for (int g = 0; g < 2; g++)
                #pragma unroll
                for (int j = 0; j < 8; j++)
                    #pragma unroll
                    for (int c = 0; c < 4; c++) sf[g][j][c] = 0.f;

            #pragma unroll
            for (int kt = 0; kt < 4; kt++) {
                #pragma unroll
                for (int jp = 0; jp < 4; jp++) {
                    uint32_t rr[4];
                    ldsm4(rr, s2u(kb + (jp * 16 + (lane & 15)) * QKV_STRIDE +
                                  kt * 16 + ((lane >> 4) << 3)));
                    uint32_t blo[2] = { rr[0], rr[2] };
                    uint32_t bhi[2] = { rr[1], rr[3] };
                    mma_f16(sf[0][jp * 2], aq[0][kt], blo);
                    mma_f16(sf[0][jp * 2 + 1], aq[0][kt], bhi);
                    mma_f16(sf[1][jp * 2], aq[1][kt], blo);
                    mma_f16(sf[1][jp * 2 + 1], aq[1][kt], bhi);
                }
            }

            // softmax + P frags per group (no l-MMA here: PV starts sooner)
            uint32_t pa[2][4][4];
            #pragma unroll
            for (int g = 0; g < 2; g++) {
                float mx0 = -1e30f, mx1 = -1e30f;
                #pragma unroll
                for (int j = 0; j < 8; j++) {
                    mx0 = fmaxf(mx0, fmaxf(sf[g][j][0], sf[g][j][1]));
                    mx1 = fmaxf(mx1, fmaxf(sf[g][j][2], sf[g][j][3]));
                }
                mx0 = fmaxf(mx0, __shfl_xor_sync(0xffffffffu, mx0, 1, 4));
                mx0 = fmaxf(mx0, __shfl_xor_sync(0xffffffffu, mx0, 2, 4));
                mx1 = fmaxf(mx1, __shfl_xor_sync(0xffffffffu, mx1, 1, 4));
                mx1 = fmaxf(mx1, __shfl_xor_sync(0xffffffffu, mx1, 2, 4));

                if (mx0 > m_[g][0]) {
                    float alpha = ex2f((m_[g][0] - mx0) * cs_);
                    m_[g][0] = mx0; l_[g][0] *= alpha;
                    #pragma unroll
                    for (int j = 0; j < 8; j++) { of[g][j][0] *= alpha; of[g][j][1] *= alpha; }
                }
                if (mx1 > m_[g][1]) {
                    float alpha = ex2f((m_[g][1] - mx1) * cs_);
                    m_[g][1] = mx1; l_[g][1] *= alpha;
                    #pragma unroll
                    for (int j = 0; j < 8; j++) { of[g][j][2] *= alpha; of[g][j][3] *= alpha; }
                }

                float nm0 = -m_[g][0] * cs_, nm1 = -m_[g][1] * cs_;
                #pragma unroll
                for (int kk = 0; kk < 4; kk++) {
                    int ja = 2 * kk, jb = 2 * kk + 1;
                    pa[g][kk][0] = h2exp2(pack_h2(fmaf(sf[g][ja][0], cs_, nm0),
                                                  fmaf(sf[g][ja][1], cs_, nm0)));
                    pa[g][kk][1] = h2exp2(pack_h2(fmaf(sf[g][ja][2], cs_, nm1),
                                                  fmaf(sf[g][ja][3], cs_, nm1)));
                    pa[g][kk][2] = h2exp2(pack_h2(fmaf(sf[g][jb][0], cs_, nm0),
                                                  fmaf(sf[g][jb][1], cs_, nm0)));
                    pa[g][kk][3] = h2exp2(pack_h2(fmaf(sf[g][jb][2], cs_, nm1),
                                                  fmaf(sf[g][jb][3], cs_, nm1)));
                }
            }

            // O += P @ V (both groups; V frags loaded once)
            #pragma unroll
            for (int kk = 0; kk < 4; kk++) {
                #pragma unroll
                for (int jp = 0; jp < 4; jp++) {
                    uint32_t rr[4];
                    ldsm4t(rr, s2u(vb + (kk * 16 + (lane & 15)) * QKV_STRIDE +
                                   jp * 16 + ((lane >> 4) << 3)));
                    uint32_t blo[2] = { rr[0], rr[1] };
                    uint32_t bhi[2] = { rr[2], rr[3] };
                    mma_f16(of[0][jp * 2], pa[0][kk], blo);
                    mma_f16(of[0][jp * 2 + 1], pa[0][kk], bhi);
                    mma_f16(of[1][jp * 2], pa[1][kk], blo);
                    mma_f16(of[1][jp * 2 + 1], pa[1][kk], bhi);
                }
            }

            // row sums l += P @ ones (after PV; same accumulation order)
            #pragma unroll
            for (int g = 0; g < 2; g++) {
                float lacc[4] = { 0.f, 0.f, 0.f, 0.f };
                #pragma unroll
                for (int kk = 0; kk < 4; kk++)
                    mma_f16(lacc, pa[g][kk], ob);
                l_[g][0] += lacc[0];
                l_[g][1] += lacc[2];
            }
        }

        #pragma unroll
        for (int g = 0; g < 2; g++) {
            float inv0 = 1.f / l_[g][0], inv1 = 1.f / l_[g][1];
            int r = wid * 32 + g * 16 + (lane >> 2);
            int c0 = (lane & 3) * 2;
            #pragma unroll
            for (int j = 0; j < 8; j++) {
                int col = j * 8 + c0;
                *(__half2*)(O + base + (size_t)(q0 + r) * D_ + col) =
                    __floats2half2_rn(of[g][j][0] * inv0, of[g][j][1] * inv0);
                *(__half2*)(O + base + (size_t)(q0 + r + 8) * D_ + col) =
                    __floats2half2_rn(of[g][j][2] * inv1, of[g][j][3] * inv1);
            }
        }
    }
}

// ---------------------------------------------------------------------------
// Launch
// ---------------------------------------------------------------------------
extern "C" void kernel_launch(void* const* d_in, const int* in_sizes, int n_in,
                              void* d_out, int out_size)
{
    const float* x  = (const float*)d_in[0];
    const float* fr = (const float*)d_in[1];
    const float* wq = (const float*)d_in[2];
    const float* bq = (const float*)d_in[3];
    const float* wk = (const float*)d_in[4];
    const float* bk = (const float*)d_in[5];
    const float* wv = (const float*)d_in[6];
    const float* bv = (const float*)d_in[7];
    const float* wo = (const float*)d_in[8];
    const float* bo = (const float*)d_in[9];
    float* out = (float*)d_out;

    __half *xh, *wqh, *wkh, *wvh, *woh, *qh, *kh, *vh, *oh;
    cudaGetSymbolAddress((void**)&xh,  g_xh);
    cudaGetSymbolAddress((void**)&wqh, g_wqh);
    cudaGetSymbolAddress((void**)&wkh, g_wkh);
    cudaGetSymbolAddress((void**)&wvh, g_wvh);
    cudaGetSymbolAddress((void**)&woh, g_woh);
    cudaGetSymbolAddress((void**)&qh,  g_qh);
    cudaGetSymbolAddress((void**)&kh,  g_kh);
    cudaGetSymbolAddress((void**)&vh,  g_vh);
    cudaGetSymbolAddress((void**)&oh,  g_oh);

    cudaFuncSetAttribute(gemm_qkv_p,
                         cudaFuncAttributeMaxDynamicSharedMemorySize, GEMM_SMEM);
    cudaFuncSetAttribute(gemm_o,
                         cudaFuncAttributeMaxDynamicSharedMemorySize, GEMM_SMEM);
    cudaFuncSetAttribute(attn_mma_p,
                         cudaFuncAttributeMaxDynamicSharedMemorySize, ATTN_SMEM);

    int dev = 0, nsm = 148;
    cudaGetDevice(&dev);
    cudaDeviceGetAttribute(&nsm, cudaDevAttrMultiProcessorCount, dev);
    int pgrid = 2 * nsm;   // 2 CTAs/SM residency for both persistent kernels

    const int NTOT = B_ * S_ * D_ + 4 * D_ * D_;   // 8M elements
    conv_all<<<NTOT / 4096, 256>>>(x, wq, wk, wv, wo, xh, wqh, wkh, wvh, woh);

    gemm_qkv_p<<<pgrid, 128, GEMM_SMEM>>>(xh, wqh, wkh, wvh, bq, bk, bv, fr,
                                          qh, kh, vh);

    attn_mma_p<<<pgrid, 128, ATTN_SMEM>>>(qh, kh, vh, oh);

    dim3 gg(D_ / 128, (B_ * S_) / 128);      // (8, 32)
    gemm_o<<<gg, 128, GEMM_SMEM>>>(oh, woh, bo, out);
}